// round 1
// baseline (speedup 1.0000x reference)
#include <cuda_runtime.h>

#define NUM_LAYERS 24
#define LN_EPS 1e-5f

// Shapes (fixed by the problem):
//   x    : [256, 8192, 5]  -> 2,097,152 rows of 5 floats
//   ln_w : [24, 4], ln_b : [24, 4]
//   W1   : [64, 5],  b1 : [64]
//   W2   : [32, 64], b2 : [32]
//   W3   : [1, 32],  b3 : [1]
//   out  : [256, 8192] float32

#define THREADS 256

__global__ __launch_bounds__(THREADS) void router_kernel(
    const float* __restrict__ x,
    const float* __restrict__ ln_w,
    const float* __restrict__ ln_b,
    const float* __restrict__ W1,
    const float* __restrict__ b1,
    const float* __restrict__ W2,
    const float* __restrict__ b2,
    const float* __restrict__ W3,
    const float* __restrict__ b3,
    float* __restrict__ out,
    int n_rows)
{
    // ---- shared staging ----
    __shared__ float sW1[64 * 5];      // 320
    __shared__ float sb1[64];
    __shared__ float sW2[32 * 64];     // 2048, row-major [j][k]
    __shared__ float sb2[32];
    __shared__ float sW3[32];
    __shared__ float sb3;
    __shared__ float sLnW[NUM_LAYERS * 4];
    __shared__ float sLnB[NUM_LAYERS * 4];
    __shared__ float sx[THREADS * 5];  // 1280 floats, block's input slab

    const int tid = threadIdx.x;

    // cooperative weight loads (once per block)
    for (int i = tid; i < 64 * 5; i += THREADS) sW1[i] = W1[i];
    for (int i = tid; i < 32 * 64; i += THREADS) sW2[i] = W2[i];
    if (tid < 64) sb1[tid] = b1[tid];
    if (tid < 32) { sb2[tid] = b2[tid]; sW3[tid] = W3[tid]; }
    if (tid == 0) sb3 = b3[0];
    for (int i = tid; i < NUM_LAYERS * 4; i += THREADS) {
        sLnW[i] = ln_w[i];
        sLnB[i] = ln_b[i];
    }

    // coalesced input slab load: 256 rows * 5 floats = 1280 contiguous floats
    const long long base_row = (long long)blockIdx.x * THREADS;
    const float* xin = x + base_row * 5;
    #pragma unroll
    for (int i = tid; i < THREADS * 5; i += THREADS) sx[i] = xin[i];

    __syncthreads();

    const long long row = base_row + tid;
    if (row >= n_rows) return;

    // ---- per-row features (stride-5 smem read: gcd(5,32)=1, conflict-free) ----
    const float f0 = sx[tid * 5 + 0];
    const float f1 = sx[tid * 5 + 1];
    const float f2 = sx[tid * 5 + 2];
    const float f3 = sx[tid * 5 + 3];
    const float pos = sx[tid * 5 + 4];

    // layernorm over the 4 feats (biased variance, matches jnp.mean of squares)
    const float mean = (f0 + f1 + f2 + f3) * 0.25f;
    const float d0 = f0 - mean, d1 = f1 - mean, d2 = f2 - mean, d3 = f3 - mean;
    const float var = (d0 * d0 + d1 * d1 + d2 * d2 + d3 * d3) * 0.25f;
    const float rstd = rsqrtf(var + LN_EPS);

    // layer id: truncate like .astype(int32), clip to [0, 23]
    int lid = (int)(pos * (float)NUM_LAYERS);
    lid = max(0, min(NUM_LAYERS - 1, lid));

    const float n0 = d0 * rstd * sLnW[lid * 4 + 0] + sLnB[lid * 4 + 0];
    const float n1 = d1 * rstd * sLnW[lid * 4 + 1] + sLnB[lid * 4 + 1];
    const float n2 = d2 * rstd * sLnW[lid * 4 + 2] + sLnB[lid * 4 + 2];
    const float n3 = d3 * rstd * sLnW[lid * 4 + 3] + sLnB[lid * 4 + 3];

    // ---- layer 1: 5 -> 64, relu ----
    float h1[64];
    #pragma unroll
    for (int j = 0; j < 64; j++) {
        const float* w = &sW1[j * 5];
        float acc = sb1[j];
        acc += w[0] * n0;
        acc += w[1] * n1;
        acc += w[2] * n2;
        acc += w[3] * n3;
        acc += w[4] * pos;
        h1[j] = fmaxf(acc, 0.0f);
    }

    // ---- layer 2: 64 -> 32, relu (float4 weight reads from smem, broadcast) ----
    float h2[32];
    #pragma unroll
    for (int j = 0; j < 32; j++) {
        const float4* w4 = reinterpret_cast<const float4*>(&sW2[j * 64]);
        float acc = sb2[j];
        #pragma unroll
        for (int k4 = 0; k4 < 16; k4++) {
            const float4 w = w4[k4];
            acc += w.x * h1[k4 * 4 + 0];
            acc += w.y * h1[k4 * 4 + 1];
            acc += w.z * h1[k4 * 4 + 2];
            acc += w.w * h1[k4 * 4 + 3];
        }
        h2[j] = fmaxf(acc, 0.0f);
    }

    // ---- layer 3: 32 -> 1 ----
    float acc = sb3;
    #pragma unroll
    for (int j = 0; j < 32; j++) acc += sW3[j] * h2[j];

    out[row] = acc;
}

extern "C" void kernel_launch(void* const* d_in, const int* in_sizes, int n_in,
                              void* d_out, int out_size)
{
    const float* x    = (const float*)d_in[0];
    const float* ln_w = (const float*)d_in[1];
    const float* ln_b = (const float*)d_in[2];
    const float* W1   = (const float*)d_in[3];
    const float* b1   = (const float*)d_in[4];
    const float* W2   = (const float*)d_in[5];
    const float* b2   = (const float*)d_in[6];
    const float* W3   = (const float*)d_in[7];
    const float* b3   = (const float*)d_in[8];
    float* out = (float*)d_out;

    const int n_rows = out_size;              // 256 * 8192
    const int blocks = (n_rows + THREADS - 1) / THREADS;

    router_kernel<<<blocks, THREADS>>>(x, ln_w, ln_b, W1, b1, W2, b2, W3, b3,
                                       out, n_rows);
}